// round 2
// baseline (speedup 1.0000x reference)
#include <cuda_runtime.h>
#include <cstdint>

// Lorenz96, 100 steps of Kutta-3/8 RK4, dt=0.01, F=8. Packed f32x2 version.
//
// Strided pairing: per row (40 elems), pair v_j = (x[j], x[j+20]), j=0..19.
// Key property: a shift by s elements maps v_j -> v_{j+s}, i.e. every shifted
// operand is ANOTHER EXISTING register pair (no repacking MOVs). The cyclic
// wrap only affects pairs crossing the j=0/20 boundary, where the shifted pair
// is swap(v) — handled by 2 SELs on the shuffled halo words (idle ALU pipe).
//
// 4 lanes per row, 5 pairs per lane (40 = 4*10). Halos via __shfl_sync width 4.
// All arithmetic is fma.rn.f32x2 / add.rn.f32x2 (PTX-only packed fp32, 2x the
// scalar FFMA rate). State in registers for all 100 steps.

#define L96_DIM   40
#define L96_STEPS 100

typedef unsigned long long ull;

__device__ __forceinline__ ull fma2(ull a, ull b, ull c) {
    ull d; asm("fma.rn.f32x2 %0, %1, %2, %3;" : "=l"(d) : "l"(a), "l"(b), "l"(c)); return d;
}
__device__ __forceinline__ ull add2(ull a, ull b) {
    ull d; asm("add.rn.f32x2 %0, %1, %2;" : "=l"(d) : "l"(a), "l"(b)); return d;
}
__device__ __forceinline__ ull pack2(float lo, float hi) {
    ull d; asm("mov.b64 %0, {%1, %2};" : "=l"(d) : "f"(lo), "f"(hi)); return d;
}
__device__ __forceinline__ float lo2(ull v) { return __uint_as_float((unsigned)v); }
__device__ __forceinline__ float hi2(ull v) { return __uint_as_float((unsigned)(v >> 32)); }
__device__ __forceinline__ ull dup2(float c) { return pack2(c, c); }

// Fetch pair `v` from lane (sub+off)&3 of the 4-lane group; if `swap`, return
// it half-swapped (this lane sits at the cyclic boundary).
__device__ __forceinline__ ull halo(ull v, int src, bool swap) {
    const unsigned m = 0xffffffffu;
    float rlo = __shfl_sync(m, lo2(v), src, 4);
    float rhi = __shfl_sync(m, hi2(v), src, 4);
    float a = swap ? rhi : rlo;
    float b = swap ? rlo : rhi;
    return pack2(a, b);
}

// d_i = (x[i+1] - x[i-2]) * x[i-1] - x_i + F, cyclic — packed over 5 pairs.
// src and dst must be distinct arrays.
__device__ __forceinline__ void l96_rhs(const ull src[5], ull dst[5], int sub,
                                        ull NEG1, ull F2) {
    // halo pairs (the only cross-lane / wrap-affected shifted operands)
    ull hl3 = halo(src[3], sub + 3, sub == 0);  // left neighbor P3 -> XM2[0]
    ull hl4 = halo(src[4], sub + 3, sub == 0);  // left neighbor P4 -> XM1[0], XM2[1]
    ull hr0 = halo(src[0], sub + 1, sub == 3);  // right neighbor P0 -> XP1[4]

    ull xp1[5] = { src[1], src[2], src[3], src[4], hr0 };
    ull xm1[5] = { hl4,    src[0], src[1], src[2], src[3] };
    ull xm2[5] = { hl3,    hl4,    src[0], src[1], src[2] };

    #pragma unroll
    for (int k = 0; k < 5; k++) {
        ull diff = fma2(xm2[k], NEG1, xp1[k]);   // x[i+1] - x[i-2]
        ull t    = fma2(src[k], NEG1, F2);       // F - x[i]
        dst[k]   = fma2(diff, xm1[k], t);
    }
}

__global__ void __launch_bounds__(128)
lorenz96_kernel(const float* __restrict__ x_in, float* __restrict__ x_out, int batch) {
    int tid = blockIdx.x * blockDim.x + threadIdx.x;
    int row = tid >> 2;        // 4 lanes per row
    int sub = tid & 3;
    if (row >= batch) return;

    const float DT = 0.01f;
    const ull NEG1  = dup2(-1.0f);
    const ull F2    = dup2(8.0f);
    const ull DT2   = dup2(DT);
    const ull DT3   = dup2(DT / 3.0f);
    const ull NDT3  = dup2(-DT / 3.0f);
    const ull THREE = dup2(3.0f);
    const ull DT8   = dup2(DT / 8.0f);

    const float* xp = x_in  + (size_t)row * L96_DIM + sub * 5;
    float*       op = x_out + (size_t)row * L96_DIM + sub * 5;

    // load strided pairs: pair k = (x[5*sub+k], x[5*sub+k+20])
    ull X[5], Y[5], S[5], A[5], D[5];
    #pragma unroll
    for (int k = 0; k < 5; k++) X[k] = pack2(xp[k], xp[k + 20]);

    #pragma unroll 1
    for (int step = 0; step < L96_STEPS; step++) {
        // ---- stage 1: k1 = f(x);  y2 = x + (dt/3)*k1 ----
        l96_rhs(X, S, sub, NEG1, F2);                 // S = k1
        #pragma unroll
        for (int k = 0; k < 5; k++) Y[k] = fma2(DT3, S[k], X[k]);

        // ---- stage 2: k2 = f(y2) ----
        l96_rhs(Y, D, sub, NEG1, F2);                 // D = k2
        #pragma unroll
        for (int k = 0; k < 5; k++) {
            Y[k] = fma2(DT2, D[k], fma2(NDT3, S[k], X[k])); // y3 = x + dt*k2 - dt/3*k1
            A[k] = fma2(D[k], NEG1, S[k]);            // a = k1 - k2
            S[k] = fma2(THREE, D[k], S[k]);           // s = k1 + 3*k2
        }

        // ---- stage 3: k3 = f(y3) ----
        l96_rhs(Y, D, sub, NEG1, F2);                 // D = k3
        #pragma unroll
        for (int k = 0; k < 5; k++) {
            S[k] = fma2(THREE, D[k], S[k]);           // s += 3*k3
            Y[k] = fma2(DT2, add2(A[k], D[k]), X[k]); // y4 = x + dt*(k1-k2+k3)
        }

        // ---- stage 4: k4 = f(y4);  x += dt*(k1+3k2+3k3+k4)/8 ----
        l96_rhs(Y, D, sub, NEG1, F2);                 // D = k4
        #pragma unroll
        for (int k = 0; k < 5; k++)
            X[k] = fma2(DT8, add2(S[k], D[k]), X[k]);
    }

    #pragma unroll
    for (int k = 0; k < 5; k++) {
        op[k]      = lo2(X[k]);
        op[k + 20] = hi2(X[k]);
    }
}

extern "C" void kernel_launch(void* const* d_in, const int* in_sizes, int n_in,
                              void* d_out, int out_size) {
    const float* x = (const float*)d_in[0];
    float* out = (float*)d_out;
    int batch = in_sizes[0] / L96_DIM;       // 262144
    int total_threads = batch * 4;           // 4 lanes per row
    int block = 128;
    int grid = (total_threads + block - 1) / block;
    lorenz96_kernel<<<grid, block>>>(x, out, batch);
}

// round 3
// speedup vs baseline: 1.1404x; 1.1404x over previous
#include <cuda_runtime.h>

// Lorenz96, 100 steps of Kutta-3/8 RK4, dt=0.01, F=8.
// 2 lanes per row, 20 contiguous elements per lane (40 = 2*20), scalar fp32.
// Cyclic halo: with 2 lanes/row, left and right neighbor are the SAME partner
// lane -> all 3 halo words come from one shfl.bfly partner exchange (width=2).
// RHS is evaluated in place with two rolling temps (o_m2, o_m1), so live state
// is only 4 arrays of 20 floats (X, S, A, Y) -> ~100 regs, no spills.
// State lives in registers across all 100 steps; pure fp32 FMA-pipe kernel.

#define L96_DIM   40
#define L96_EPL   20
#define L96_STEPS 100

// Out-of-place RHS: dst = f(src), src preserved. (stage 1: k1 = f(x))
__device__ __forceinline__ void l96_rhs_oop(const float src[L96_EPL], float dst[L96_EPL]) {
    const unsigned m = 0xffffffffu;
    // partner lane holds the other 20 elements of this row
    float h18 = __shfl_xor_sync(m, src[18], 1, 2);  // x[i0-2] for i=0
    float h19 = __shfl_xor_sync(m, src[19], 1, 2);  // x[i0-1] for i=0
    float h0  = __shfl_xor_sync(m, src[0],  1, 2);  // x[i0+20] for i=19
    float om2 = h18, om1 = h19;
    #pragma unroll
    for (int i = 0; i < L96_EPL; i++) {
        float cur = src[i];
        float nxt = (i < L96_EPL - 1) ? src[i + 1] : h0;
        dst[i] = fmaf(nxt - om2, om1, 8.0f - cur);
        om2 = om1; om1 = cur;       // register renames after unroll
    }
}

// In-place RHS: v = f(v). Rolling temps preserve the two overwritten neighbors.
__device__ __forceinline__ void l96_rhs_ip(float v[L96_EPL]) {
    const unsigned m = 0xffffffffu;
    float h18 = __shfl_xor_sync(m, v[18], 1, 2);
    float h19 = __shfl_xor_sync(m, v[19], 1, 2);
    float h0  = __shfl_xor_sync(m, v[0],  1, 2);
    float om2 = h18, om1 = h19;
    #pragma unroll
    for (int i = 0; i < L96_EPL; i++) {
        float cur = v[i];
        float nxt = (i < L96_EPL - 1) ? v[i + 1] : h0;
        v[i] = fmaf(nxt - om2, om1, 8.0f - cur);
        om2 = om1; om1 = cur;
    }
}

__global__ void __launch_bounds__(128)
lorenz96_kernel(const float* __restrict__ x_in, float* __restrict__ x_out, int batch) {
    int tid = blockIdx.x * blockDim.x + threadIdx.x;
    int row = tid >> 1;         // 2 lanes per row
    int sub = tid & 1;
    if (row >= batch) return;

    const float DT   = 0.01f;
    const float DT3  = 0.01f / 3.0f;
    const float NDT3 = -(0.01f / 3.0f);
    const float DT8  = 0.01f / 8.0f;

    const float* xp = x_in  + (size_t)row * L96_DIM + sub * L96_EPL;
    float*       op = x_out + (size_t)row * L96_DIM + sub * L96_EPL;

    float X[L96_EPL], S[L96_EPL], A[L96_EPL], Y[L96_EPL];
    #pragma unroll
    for (int i = 0; i < L96_EPL; i++) X[i] = xp[i];

    #pragma unroll 1
    for (int step = 0; step < L96_STEPS; step++) {
        // ---- stage 1: k1 = f(x); y2 = x + (dt/3)*k1 ----
        l96_rhs_oop(X, S);                       // S = k1
        #pragma unroll
        for (int i = 0; i < L96_EPL; i++) Y[i] = fmaf(DT3, S[i], X[i]);

        // ---- stage 2: k2 = f(y2) ----
        l96_rhs_ip(Y);                           // Y = k2
        #pragma unroll
        for (int i = 0; i < L96_EPL; i++) {
            float k2 = Y[i];
            A[i] = S[i] - k2;                    // a = k1 - k2
            Y[i] = fmaf(DT, k2, fmaf(NDT3, S[i], X[i]));  // y3 = x + dt*k2 - dt/3*k1
            S[i] = fmaf(3.0f, k2, S[i]);         // s = k1 + 3*k2
        }

        // ---- stage 3: k3 = f(y3) ----
        l96_rhs_ip(Y);                           // Y = k3
        #pragma unroll
        for (int i = 0; i < L96_EPL; i++) {
            float k3 = Y[i];
            S[i] = fmaf(3.0f, k3, S[i]);         // s += 3*k3
            Y[i] = fmaf(DT, A[i] + k3, X[i]);    // y4 = x + dt*(k1 - k2 + k3)
        }

        // ---- stage 4: k4 = f(y4); x += dt*(k1+3k2+3k3+k4)/8 ----
        l96_rhs_ip(Y);                           // Y = k4
        #pragma unroll
        for (int i = 0; i < L96_EPL; i++)
            X[i] = fmaf(DT8, S[i] + Y[i], X[i]);
    }

    #pragma unroll
    for (int i = 0; i < L96_EPL; i++) op[i] = X[i];
}

extern "C" void kernel_launch(void* const* d_in, const int* in_sizes, int n_in,
                              void* d_out, int out_size) {
    const float* x = (const float*)d_in[0];
    float* out = (float*)d_out;
    int batch = in_sizes[0] / L96_DIM;       // 262144
    int total_threads = batch * 2;           // 2 lanes per row
    int block = 128;
    int grid = (total_threads + block - 1) / block;
    lorenz96_kernel<<<grid, block>>>(x, out, batch);
}